// round 15
// baseline (speedup 1.0000x reference)
#include <cuda_runtime.h>
#include <cuda_bf16.h>
#include <cstdint>

// Shapes (fixed by the problem)
#define B_   2
#define S_   2048
#define H_   4096
#define NH_  32
#define NKV_ 8
#define HD_  128
#define BS_  (B_ * S_)          // 4096 rows
#define KV_  (NKV_ * HD_)       // 1024

// ===========================================================================
// Base-target tensor-core primitives: mma.sync + ldmatrix + cp.async.
// (tcgen05 needs compute_103a virtual arch; harness compiles compute_103.)
// ===========================================================================
__device__ __forceinline__ uint32_t smem_u32(const void* p) {
    uint32_t a;
    asm("{ .reg .u64 t; cvta.to.shared.u64 t, %1; cvt.u32.u64 %0, t; }"
        : "=r"(a) : "l"(p));
    return a;
}
__device__ __forceinline__ void cp16(uint32_t s, const void* g) {
    asm volatile("cp.async.cg.shared.global [%0], [%1], 16;" :: "r"(s), "l"(g));
}
#define CP_COMMIT()  asm volatile("cp.async.commit_group;" ::: "memory")
#define CP_WAIT(n)   asm volatile("cp.async.wait_group %0;" :: "n"(n) : "memory")

__device__ __forceinline__ void ldm_x4(uint32_t* r, uint32_t addr) {
    asm volatile("ldmatrix.sync.aligned.m8n8.x4.shared.b16 {%0,%1,%2,%3}, [%4];"
                 : "=r"(r[0]), "=r"(r[1]), "=r"(r[2]), "=r"(r[3]) : "r"(addr));
}
__device__ __forceinline__ void ldm_x4_t(uint32_t* r, uint32_t addr) {
    asm volatile("ldmatrix.sync.aligned.m8n8.x4.trans.shared.b16 {%0,%1,%2,%3}, [%4];"
                 : "=r"(r[0]), "=r"(r[1]), "=r"(r[2]), "=r"(r[3]) : "r"(addr));
}
__device__ __forceinline__ void mma_bf16(float* c, const uint32_t* a,
                                         const uint32_t* b) {
    asm volatile(
        "mma.sync.aligned.m16n8k16.row.col.f32.bf16.bf16.f32 "
        "{%0,%1,%2,%3}, {%4,%5,%6,%7}, {%8,%9}, {%0,%1,%2,%3};"
        : "+f"(c[0]), "+f"(c[1]), "+f"(c[2]), "+f"(c[3])
        : "r"(a[0]), "r"(a[1]), "r"(a[2]), "r"(a[3]), "r"(b[0]), "r"(b[1]));
}

// Split two fp32 into packed bf16x2 hi and lo(residual) words. x -> low half.
__device__ __forceinline__ void split2(float x, float y, uint32_t& hi, uint32_t& lo) {
    __nv_bfloat16 hx = __float2bfloat16(x), hy = __float2bfloat16(y);
    __nv_bfloat162 hp = __nv_bfloat162(hx, hy);
    __nv_bfloat162 lp = __floats2bfloat162_rn(x - __bfloat162float(hx),
                                              y - __bfloat162float(hy));
    hi = *(uint32_t*)&hp;
    lo = *(uint32_t*)&lp;
}

// ===========================================================================
// Scratch (device globals — no allocation allowed)
// ===========================================================================
__device__ float  g_q [BS_ * NH_  * HD_];
__device__ float  g_k [BS_ * NKV_ * HD_];
__device__ float  g_v [BS_ * NKV_ * HD_];
__device__ float2 g_cs[S_ * 64];

// bf16 hi/lo splits
__device__ __nv_bfloat16 g_hs_hi[BS_ * H_],  g_hs_lo[BS_ * H_];
__device__ __nv_bfloat16 g_ao_hi[BS_ * H_],  g_ao_lo[BS_ * H_];   // written by attention
__device__ __nv_bfloat16 g_wq_hi[H_ * H_],   g_wq_lo[H_ * H_];
__device__ __nv_bfloat16 g_wk_hi[KV_ * H_],  g_wk_lo[KV_ * H_];
__device__ __nv_bfloat16 g_wv_hi[KV_ * H_],  g_wv_lo[KV_ * H_];
__device__ __nv_bfloat16 g_wo_hi[H_ * H_],   g_wo_lo[H_ * H_];

// ===========================================================================
// fp32 -> bf16 hi/lo elementwise split
// ===========================================================================
__global__ void split_k(const float* __restrict__ src,
                        __nv_bfloat16* __restrict__ hi,
                        __nv_bfloat16* __restrict__ lo, int n) {
    int i = blockIdx.x * blockDim.x + threadIdx.x;
    if (i >= n) return;
    float a = src[i];
    __nv_bfloat16 h = __float2bfloat16(a);
    hi[i] = h;
    lo[i] = __float2bfloat16(a - __bfloat162float(h));
}

// fp32 [K][N] -> transposed bf16 hi/lo [N][K]
__global__ void transpose_split_k(const float* __restrict__ src,
                                  __nv_bfloat16* __restrict__ hi,
                                  __nv_bfloat16* __restrict__ lo,
                                  int K, int N) {
    __shared__ float t[32][33];
    int k0 = blockIdx.y * 32, n0 = blockIdx.x * 32;
    int tx = threadIdx.x, ty = threadIdx.y;       // block (32, 8)
#pragma unroll
    for (int i = ty; i < 32; i += 8)
        t[i][tx] = src[(size_t)(k0 + i) * N + n0 + tx];
    __syncthreads();
#pragma unroll
    for (int i = ty; i < 32; i += 8) {
        float a = t[tx][i];
        __nv_bfloat16 h = __float2bfloat16(a);
        size_t o = (size_t)(n0 + i) * K + k0 + tx;
        hi[o] = h;
        lo[o] = __float2bfloat16(a - __bfloat162float(h));
    }
}

// ===========================================================================
// bf16-3-split GEMM on mma.sync.m16n8k16.
// PERSISTENT: grid = min(tiles, 296); each CTA loops over 128x128 C tiles
// (kills wave quantization: Q/WO GEMMs were 3.46 waves of 296).
// 4-stage K16 cp.async pipeline, one __syncthreads per stage.
// DRAIN FIX vs R14: iterations with no new load commit an EMPTY group so
// CP_WAIT(2) always guarantees stage ks has landed (R14 relied on timing).
// __launch_bounds__(256, 2): force <=128 regs for 2-CTA/SM co-residency.
// Stage stride 24 bf16 (48B) -> ldmatrix conflict-free.
// ===========================================================================
#define GLD2    24
#define ARR2_B  (128 * GLD2 * 2)      // 6144 B per array per stage
#define STG2_B  (4 * ARR2_B)          // 24576 B (Ah, Al, Bh, Bl)
#define NSTG    4
#define GSMEM_B (NSTG * STG2_B)       // 98304 B
#define GEMM_GRID_MAX 296

__device__ __forceinline__ void g2_load(
    uint32_t sb, const __nv_bfloat16* Ah, const __nv_bfloat16* Al,
    const __nv_bfloat16* Bh, const __nv_bfloat16* Bl,
    int m0, int n0, int ks, int Kdim, int tid) {
    const int row = tid >> 1;                     // 0..127
    const int ch  = tid & 1;                      // 16B chunk (8 bf16)
    const uint32_t so = (uint32_t)(row * GLD2) * 2 + (uint32_t)ch * 16;
    const size_t gao = (size_t)(m0 + row) * Kdim + ks * 16 + ch * 8;
    const size_t gbo = (size_t)(n0 + row) * Kdim + ks * 16 + ch * 8;
    cp16(sb + 0 * ARR2_B + so, Ah + gao);
    cp16(sb + 1 * ARR2_B + so, Al + gao);
    cp16(sb + 2 * ARR2_B + so, Bh + gbo);
    cp16(sb + 3 * ARR2_B + so, Bl + gbo);
}

__global__ __launch_bounds__(256, 2)
void gemm_bf16_mma(const __nv_bfloat16* __restrict__ Ahi,
                   const __nv_bfloat16* __restrict__ Alo,
                   const __nv_bfloat16* __restrict__ Bhi,
                   const __nv_bfloat16* __restrict__ Blo,
                   float* __restrict__ C, int Mdim, int Ndim, int Kdim) {
    extern __shared__ char smem[];
    const uint32_t sb0 = smem_u32(smem);

    const int tid  = threadIdx.x;
    const int lane = tid & 31;
    const int wid  = tid >> 5;
    const int wm0  = (wid >> 2) * 64;
    const int wn0  = (wid & 3) * 32;

    const int rowA  = lane & 15;
    const int koffA = (lane & 16) ? 8 : 0;
    const int rowB  = (lane & 7) + ((lane & 16) ? 8 : 0);
    const int koffB = (lane & 8) ? 8 : 0;
    const uint32_t aoff = (uint32_t)((wm0 + rowA) * GLD2 + koffA) * 2;
    const uint32_t boff = (uint32_t)((wn0 + rowB) * GLD2 + koffB) * 2;

    const int ntN = Ndim >> 7;
    const int ntiles = (Mdim >> 7) * ntN;
    const int nks = Kdim >> 4;                    // K / 16 stages

    for (int t = blockIdx.x; t < ntiles; t += gridDim.x) {
        const int m0 = (t / ntN) * 128;
        const int n0 = (t % ntN) * 128;

        float acc[4][4][4];
#pragma unroll
        for (int i = 0; i < 4; i++)
#pragma unroll
            for (int j = 0; j < 4; j++)
#pragma unroll
                for (int c = 0; c < 4; c++) acc[i][j][c] = 0.0f;

        // Prologue: 3 stages in flight
#pragma unroll
        for (int s = 0; s < NSTG - 1; s++) {
            g2_load(sb0 + s * STG2_B, Ahi, Alo, Bhi, Blo, m0, n0, s, Kdim, tid);
            CP_COMMIT();
        }

        for (int ks = 0; ks < nks; ks++) {
            CP_WAIT(2);                           // stage ks landed (invariant)
            __syncthreads();                      // buffers free CTA-wide
            if (ks + NSTG - 1 < nks) {
                g2_load(sb0 + ((ks + NSTG - 1) & (NSTG - 1)) * STG2_B,
                        Ahi, Alo, Bhi, Blo, m0, n0, ks + NSTG - 1, Kdim, tid);
                CP_COMMIT();
            } else {
                CP_COMMIT();                      // empty group: keep wait math exact
            }

            const uint32_t st = sb0 + (ks & (NSTG - 1)) * STG2_B;
            // Staged fragment loads: hi operands first -> MMAs start sooner,
            // lower peak live registers.
            uint32_t ah[4][4], bh[2][4];
#pragma unroll
            for (int nf2 = 0; nf2 < 2; nf2++)
                ldm_x4(bh[nf2], st + 2 * ARR2_B + boff + (uint32_t)(nf2 * 16 * GLD2) * 2);
#pragma unroll
            for (int mf = 0; mf < 4; mf++)
                ldm_x4(ah[mf], st + aoff + (uint32_t)(mf * 16 * GLD2) * 2);
#pragma unroll
            for (int mf = 0; mf < 4; mf++)
#pragma unroll
                for (int nf = 0; nf < 4; nf++)
                    mma_bf16(acc[mf][nf], ah[mf], &bh[nf >> 1][(nf & 1) * 2]);

            uint32_t bl[2][4];
#pragma unroll
            for (int nf2 = 0; nf2 < 2; nf2++)
                ldm_x4(bl[nf2], st + 3 * ARR2_B + boff + (uint32_t)(nf2 * 16 * GLD2) * 2);
#pragma unroll
            for (int mf = 0; mf < 4; mf++)
#pragma unroll
                for (int nf = 0; nf < 4; nf++)
                    mma_bf16(acc[mf][nf], ah[mf], &bl[nf >> 1][(nf & 1) * 2]);

            uint32_t al[4][4];
#pragma unroll
            for (int mf = 0; mf < 4; mf++)
                ldm_x4(al[mf], st + 1 * ARR2_B + aoff + (uint32_t)(mf * 16 * GLD2) * 2);
#pragma unroll
            for (int mf = 0; mf < 4; mf++)
#pragma unroll
                for (int nf = 0; nf < 4; nf++)
                    mma_bf16(acc[mf][nf], al[mf], &bh[nf >> 1][(nf & 1) * 2]);
        }
        CP_WAIT(0);                               // drain before next tile reuses buffers

        const int erow = m0 + wm0 + (lane >> 2);
        const int ecol = n0 + wn0 + (lane & 3) * 2;
#pragma unroll
        for (int mf = 0; mf < 4; mf++)
#pragma unroll
            for (int nf = 0; nf < 4; nf++) {
                float* c = acc[mf][nf];
                float* p0 = C + (size_t)(erow + mf * 16) * Ndim + ecol + nf * 8;
                float* p1 = p0 + 8 * (size_t)Ndim;
                *(float2*)p0 = make_float2(c[0], c[1]);
                *(float2*)p1 = make_float2(c[2], c[3]);
            }
        __syncthreads();                          // stores done before next tile loads
    }
}

// ===========================================================================
// RoPE table + apply (unchanged)
// ===========================================================================
__global__ void rope_table_k() {
    int i = blockIdx.x * blockDim.x + threadIdx.x;
    if (i >= S_ * 64) return;
    int p = i >> 6, d = i & 63;
    float invf = 1.0f / powf(10000.0f, (float)(2 * d) * (1.0f / 128.0f));
    float fr = (float)p * invf;
    g_cs[i] = make_float2(cosf(fr), sinf(fr));
}

__global__ void rope_apply_k(float* __restrict__ x, int nheads) {
    int i = blockIdx.x * blockDim.x + threadIdx.x;
    int total = BS_ * nheads * 64;
    if (i >= total) return;
    int d   = i & 63;
    int hh  = (i >> 6) % nheads;
    int row = (i >> 6) / nheads;
    int p   = row % S_;
    float2 cs = g_cs[p * 64 + d];
    float* base = x + ((size_t)row * nheads + hh) * HD_;
    float x1 = base[d], x2 = base[d + 64];
    base[d]      = x1 * cs.x - x2 * cs.y;
    base[d + 64] = x2 * cs.x + x1 * cs.y;
}

// ===========================================================================
// Tensor-core flash attention (unchanged from R13 — verified WIN)
// ===========================================================================
#define AT_LDA 136
#define AT_QH  0
#define AT_QL  (128 * AT_LDA)
#define AT_KH  (2 * 128 * AT_LDA)
#define AT_KL  (AT_KH + 64 * AT_LDA)
#define AT_VH  (AT_KL + 64 * AT_LDA)
#define AT_VL  (AT_VH + 64 * AT_LDA)
#define AT_SMEM_BYTES ((AT_VL + 64 * AT_LDA) * 2)   // 139264

__global__ __launch_bounds__(256)
void flash_attn_tc(const float* __restrict__ Qg, const float* __restrict__ Kg,
                   const float* __restrict__ Vg,
                   __nv_bfloat16* __restrict__ Ohi,
                   __nv_bfloat16* __restrict__ Olo) {
    extern __shared__ __nv_bfloat16 sb_at[];
    const int qi  = (int)gridDim.x - 1 - (int)blockIdx.x;   // big tiles first
    const int h   = blockIdx.y;
    const int b   = blockIdx.z;
    const int kvh = h >> 2;
    const int tid = threadIdx.x, lane = tid & 31, wid = tid >> 5;
    const int q0  = qi * 128;
    const int wm  = wid * 16;
    const float scale = 0.08838834764831845f;      // 1/sqrt(128)
    const uint32_t sbase = smem_u32(sb_at);

    // --- Stage Q tile (128 x 128 fp32 -> hi/lo bf16 smem) ---
    {
        const int row = tid >> 1, half = tid & 1;
        const float* src = Qg + ((size_t)(b * S_ + q0 + row) * NH_ + h) * HD_ + half * 64;
        __nv_bfloat16* dh = sb_at + AT_QH + row * AT_LDA + half * 64;
        __nv_bfloat16* dl = sb_at + AT_QL + row * AT_LDA + half * 64;
#pragma unroll
        for (int i = 0; i < 16; i++) {
            float4 v = *(const float4*)(src + i * 4);
            uint32_t h0, l0, h1, l1;
            split2(v.x, v.y, h0, l0);
            split2(v.z, v.w, h1, l1);
            *(uint32_t*)(dh + i * 4)     = h0;
            *(uint32_t*)(dh + i * 4 + 2) = h1;
            *(uint32_t*)(dl + i * 4)     = l0;
            *(uint32_t*)(dl + i * 4 + 2) = l1;
        }
    }

    const int rA = lane & 15;
    const int kA = (lane & 16) ? 8 : 0;
    const int rB = (lane & 7) + ((lane & 16) ? 8 : 0);
    const int kB = (lane & 8) ? 8 : 0;

    float Oa[16][4];
#pragma unroll
    for (int i = 0; i < 16; i++)
#pragma unroll
        for (int c = 0; c < 4; c++) Oa[i][c] = 0.0f;
    float m0 = -1e30f, m1 = -1e30f, l0 = 0.0f, l1 = 0.0f;

    const int row_lo = q0 + wm + (lane >> 2);
    const int row_hi = row_lo + 8;
    const int ntiles = 2 * (qi + 1);

    for (int t = 0; t < ntiles; t++) {
        const int kv0 = t * 64;
        __syncthreads();   // smem reuse guard (also orders Q stores on t==0)

        // --- Load + split K/V tile (64 x 128 fp32 each) ---
        {
            const int row = tid >> 2, qtr = tid & 3;
            const size_t go = ((size_t)(b * S_ + kv0 + row) * NKV_ + kvh) * HD_ + qtr * 32;
            const float* sk = Kg + go;
            const float* sv = Vg + go;
            __nv_bfloat16* kh = sb_at + AT_KH + row * AT_LDA + qtr * 32;
            __nv_bfloat16* kl = sb_at + AT_KL + row * AT_LDA + qtr * 32;
            __nv_bfloat16* vh = sb_at + AT_VH + row * AT_LDA + qtr * 32;
            __nv_bfloat16* vl = sb_at + AT_VL + row * AT_LDA + qtr * 32;
#pragma unroll
            for (int i = 0; i < 8; i++) {
                float4 kv4 = *(const float4*)(sk + i * 4);
                uint32_t h0, lo0, h1, lo1;
                split2(kv4.x, kv4.y, h0, lo0);
                split2(kv4.z, kv4.w, h1, lo1);
                *(uint32_t*)(kh + i * 4) = h0; *(uint32_t*)(kh + i * 4 + 2) = h1;
                *(uint32_t*)(kl + i * 4) = lo0; *(uint32_t*)(kl + i * 4 + 2) = lo1;
                float4 vv4 = *(const float4*)(sv + i * 4);
                split2(vv4.x, vv4.y, h0, lo0);
                split2(vv4.z, vv4.w, h1, lo1);
                *(uint32_t*)(vh + i * 4) = h0; *(uint32_t*)(vh + i * 4 + 2) = h1;
                *(uint32_t*)(vl + i * 4) = lo0; *(uint32_t*)(vl + i * 4 + 2) = lo1;
            }
        }
        __syncthreads();

        // --- S = Q @ K^T (3-split), m16 x n64 per warp, fp32 accum ---
        float sc[8][4];
#pragma unroll
        for (int nf = 0; nf < 8; nf++)
#pragma unroll
            for (int c = 0; c < 4; c++) sc[nf][c] = 0.0f;

#pragma unroll
        for (int ks = 0; ks < 8; ks++) {
            uint32_t ah[4], al[4];
            uint32_t aaddr = sbase + 2u * (AT_QH + (wm + rA) * AT_LDA + ks * 16 + kA);
            ldm_x4(ah, aaddr);
            ldm_x4(al, aaddr + 2u * (AT_QL - AT_QH));
            uint32_t bh[4][4], bl[4][4];
#pragma unroll
            for (int n2 = 0; n2 < 4; n2++) {
                uint32_t baddr = sbase + 2u * (AT_KH + (n2 * 16 + rB) * AT_LDA + ks * 16 + kB);
                ldm_x4(bh[n2], baddr);
                ldm_x4(bl[n2], baddr + 2u * (AT_KL - AT_KH));
            }
#pragma unroll
            for (int nf = 0; nf < 8; nf++) {
                const uint32_t* ph = &bh[nf >> 1][(nf & 1) * 2];
                const uint32_t* pl = &bl[nf >> 1][(nf & 1) * 2];
                mma_bf16(sc[nf], ah, ph);
                mma_bf16(sc[nf], ah, pl);
                mma_bf16(sc[nf], al, ph);
            }
        }

        // --- Mask + scale + online softmax ---
        float mx0 = -1e30f, mx1 = -1e30f;
#pragma unroll
        for (int nf = 0; nf < 8; nf++) {
            const int c0 = kv0 + nf * 8 + 2 * (lane & 3);
            sc[nf][0] = (c0     <= row_lo) ? sc[nf][0] * scale : -1e30f;
            sc[nf][1] = (c0 + 1 <= row_lo) ? sc[nf][1] * scale : -1e30f;
            sc[nf][2] = (c0     <= row_hi) ? sc[nf][2] * scale : -1e30f;
            sc[nf][3] = (c0 + 1 <= row_hi) ? sc[nf][3] * scale : -1e30f;
            mx0 = fmaxf(mx0, fmaxf(sc[nf][0], sc[nf][1]));
            mx1 = fmaxf(mx1, fmaxf(sc[nf][2], sc[nf][3]));
        }
        mx0 = fmaxf(mx0, __shfl_xor_sync(0xffffffffu, mx0, 1));
        mx0 = fmaxf(mx0, __shfl_xor_sync(0xffffffffu, mx0, 2));
        mx1 = fmaxf(mx1, __shfl_xor_sync(0xffffffffu, mx1, 1));
        mx1 = fmaxf(mx1, __shfl_xor_sync(0xffffffffu, mx1, 2));

        const float mn0 = fmaxf(m0, mx0), mn1 = fmaxf(m1, mx1);
        const float a0 = __expf(m0 - mn0), a1 = __expf(m1 - mn1);
        float s0 = 0.0f, s1 = 0.0f;
#pragma unroll
        for (int nf = 0; nf < 8; nf++) {
            sc[nf][0] = __expf(sc[nf][0] - mn0);
            sc[nf][1] = __expf(sc[nf][1] - mn0);
            sc[nf][2] = __expf(sc[nf][2] - mn1);
            sc[nf][3] = __expf(sc[nf][3] - mn1);
            s0 += sc[nf][0] + sc[nf][1];
            s1 += sc[nf][2] + sc[nf][3];
        }
        s0 += __shfl_xor_sync(0xffffffffu, s0, 1);
        s0 += __shfl_xor_sync(0xffffffffu, s0, 2);
        s1 += __shfl_xor_sync(0xffffffffu, s1, 1);
        s1 += __shfl_xor_sync(0xffffffffu, s1, 2);
        l0 = l0 * a0 + s0;
        l1 = l1 * a1 + s1;
        m0 = mn0; m1 = mn1;
#pragma unroll
        for (int i = 0; i < 16; i++) {
            Oa[i][0] *= a0; Oa[i][1] *= a0;
            Oa[i][2] *= a1; Oa[i][3] *= a1;
        }

        // --- O += P @ V (3-split; V via trans-ldmatrix) ---
#pragma unroll
        for (int kc = 0; kc < 4; kc++) {
            uint32_t pah[4], pal[4];
            split2(sc[2*kc][0],   sc[2*kc][1],   pah[0], pal[0]);
            split2(sc[2*kc][2],   sc[2*kc][3],   pah[1], pal[1]);
            split2(sc[2*kc+1][0], sc[2*kc+1][1], pah[2], pal[2]);
            split2(sc[2*kc+1][2], sc[2*kc+1][3], pah[3], pal[3]);
#pragma unroll
            for (int n2 = 0; n2 < 8; n2++) {
                uint32_t bvh[4], bvl[4];
                uint32_t vaddr = sbase + 2u * (AT_VH + (kc * 16 + rA) * AT_LDA + n2 * 16 + kA);
                ldm_x4_t(bvh, vaddr);
                ldm_x4_t(bvl, vaddr + 2u * (AT_VL - AT_VH));
                mma_bf16(Oa[2*n2],     pah, &bvh[0]);
                mma_bf16(Oa[2*n2],     pah, &bvl[0]);
                mma_bf16(Oa[2*n2],     pal, &bvh[0]);
                mma_bf16(Oa[2*n2 + 1], pah, &bvh[2]);
                mma_bf16(Oa[2*n2 + 1], pah, &bvl[2]);
                mma_bf16(Oa[2*n2 + 1], pal, &bvh[2]);
            }
        }
    }

    // --- Epilogue: O / l, write bf16 hi/lo directly (WO GEMM inputs) ---
    const float inv0 = 1.0f / l0, inv1 = 1.0f / l1;
    const size_t base0 = ((size_t)(b * S_ + row_lo) * NH_ + h) * HD_;
    const size_t base1 = ((size_t)(b * S_ + row_hi) * NH_ + h) * HD_;
#pragma unroll
    for (int nf = 0; nf < 16; nf++) {
        const int d = nf * 8 + 2 * (lane & 3);
        uint32_t hh, ll;
        split2(Oa[nf][0] * inv0, Oa[nf][1] * inv0, hh, ll);
        *(uint32_t*)(Ohi + base0 + d) = hh;
        *(uint32_t*)(Olo + base0 + d) = ll;
        split2(Oa[nf][2] * inv1, Oa[nf][3] * inv1, hh, ll);
        *(uint32_t*)(Ohi + base1 + d) = hh;
        *(uint32_t*)(Olo + base1 + d) = ll;
    }
}

// ===========================================================================
// Launch
// ===========================================================================
static inline int gemm_grid(int M, int N) {
    int t = (M / 128) * (N / 128);
    return t < GEMM_GRID_MAX ? t : GEMM_GRID_MAX;
}

extern "C" void kernel_launch(void* const* d_in, const int* in_sizes, int n_in,
                              void* d_out, int out_size) {
    const float* hs  = (const float*)d_in[0];
    // d_in[1] (position_ids) unused: arange(S) broadcast, computed in-kernel.
    const float* wq  = (const float*)d_in[2];
    const float* wk  = (const float*)d_in[3];
    const float* wv  = (const float*)d_in[4];
    const float* wo  = (const float*)d_in[5];
    float*       out = (float*)d_out;

    float *q, *k, *v;
    cudaGetSymbolAddress((void**)&q, g_q);
    cudaGetSymbolAddress((void**)&k, g_k);
    cudaGetSymbolAddress((void**)&v, g_v);

    __nv_bfloat16 *hsh, *hsl, *aoh, *aol;
    __nv_bfloat16 *wqh, *wql, *wkh, *wkl, *wvh, *wvl, *woh, *wol;
    cudaGetSymbolAddress((void**)&hsh, g_hs_hi);
    cudaGetSymbolAddress((void**)&hsl, g_hs_lo);
    cudaGetSymbolAddress((void**)&aoh, g_ao_hi);
    cudaGetSymbolAddress((void**)&aol, g_ao_lo);
    cudaGetSymbolAddress((void**)&wqh, g_wq_hi);
    cudaGetSymbolAddress((void**)&wql, g_wq_lo);
    cudaGetSymbolAddress((void**)&wkh, g_wk_hi);
    cudaGetSymbolAddress((void**)&wkl, g_wk_lo);
    cudaGetSymbolAddress((void**)&wvh, g_wv_hi);
    cudaGetSymbolAddress((void**)&wvl, g_wv_lo);
    cudaGetSymbolAddress((void**)&woh, g_wo_hi);
    cudaGetSymbolAddress((void**)&wol, g_wo_lo);

    cudaFuncSetAttribute(gemm_bf16_mma, cudaFuncAttributeMaxDynamicSharedMemorySize,
                         GSMEM_B);
    cudaFuncSetAttribute(flash_attn_tc, cudaFuncAttributeMaxDynamicSharedMemorySize,
                         AT_SMEM_BYTES);

    split_k<<<(BS_ * H_ + 255) / 256, 256>>>(hs, hsh, hsl, BS_ * H_);
    transpose_split_k<<<dim3(H_ / 32,  H_ / 32), dim3(32, 8)>>>(wq, wqh, wql, H_, H_);
    transpose_split_k<<<dim3(KV_ / 32, H_ / 32), dim3(32, 8)>>>(wk, wkh, wkl, H_, KV_);
    transpose_split_k<<<dim3(KV_ / 32, H_ / 32), dim3(32, 8)>>>(wv, wvh, wvl, H_, KV_);
    transpose_split_k<<<dim3(H_ / 32,  H_ / 32), dim3(32, 8)>>>(wo, woh, wol, H_, H_);

    gemm_bf16_mma<<<gemm_grid(BS_, H_),  256, GSMEM_B>>>(hsh, hsl, wqh, wql, q, BS_, H_,  H_);
    gemm_bf16_mma<<<gemm_grid(BS_, KV_), 256, GSMEM_B>>>(hsh, hsl, wkh, wkl, k, BS_, KV_, H_);
    gemm_bf16_mma<<<gemm_grid(BS_, KV_), 256, GSMEM_B>>>(hsh, hsl, wvh, wvl, v, BS_, KV_, H_);

    rope_table_k<<<(S_ * 64 + 255) / 256, 256>>>();
    rope_apply_k<<<(BS_ * NH_  * 64) / 256, 256>>>(q, NH_);
    rope_apply_k<<<(BS_ * NKV_ * 64) / 256, 256>>>(k, NKV_);

    flash_attn_tc<<<dim3(S_ / 128, NH_, B_), 256, AT_SMEM_BYTES>>>(q, k, v, aoh, aol);

    gemm_bf16_mma<<<gemm_grid(BS_, H_), 256, GSMEM_B>>>(aoh, aol, woh, wol, out, BS_, H_, H_);
}

// round 16
// speedup vs baseline: 1.0668x; 1.0668x over previous
#include <cuda_runtime.h>
#include <cuda_bf16.h>
#include <cstdint>

// Shapes (fixed by the problem)
#define B_   2
#define S_   2048
#define H_   4096
#define NH_  32
#define NKV_ 8
#define HD_  128
#define BS_  (B_ * S_)          // 4096 rows
#define KV_  (NKV_ * HD_)       // 1024
#define QKV_ (H_ + 2 * KV_)     // 6144 fused projection width

// ===========================================================================
// Base-target tensor-core primitives: mma.sync + ldmatrix + cp.async.
// (tcgen05 needs compute_103a virtual arch; harness compiles compute_103.)
// ===========================================================================
__device__ __forceinline__ uint32_t smem_u32(const void* p) {
    uint32_t a;
    asm("{ .reg .u64 t; cvta.to.shared.u64 t, %1; cvt.u32.u64 %0, t; }"
        : "=r"(a) : "l"(p));
    return a;
}
__device__ __forceinline__ void cp16(uint32_t s, const void* g) {
    asm volatile("cp.async.cg.shared.global [%0], [%1], 16;" :: "r"(s), "l"(g));
}
#define CP_COMMIT()  asm volatile("cp.async.commit_group;" ::: "memory")
#define CP_WAIT(n)   asm volatile("cp.async.wait_group %0;" :: "n"(n) : "memory")

__device__ __forceinline__ void ldm_x4(uint32_t* r, uint32_t addr) {
    asm volatile("ldmatrix.sync.aligned.m8n8.x4.shared.b16 {%0,%1,%2,%3}, [%4];"
                 : "=r"(r[0]), "=r"(r[1]), "=r"(r[2]), "=r"(r[3]) : "r"(addr));
}
__device__ __forceinline__ void ldm_x4_t(uint32_t* r, uint32_t addr) {
    asm volatile("ldmatrix.sync.aligned.m8n8.x4.trans.shared.b16 {%0,%1,%2,%3}, [%4];"
                 : "=r"(r[0]), "=r"(r[1]), "=r"(r[2]), "=r"(r[3]) : "r"(addr));
}
__device__ __forceinline__ void mma_bf16(float* c, const uint32_t* a,
                                         const uint32_t* b) {
    asm volatile(
        "mma.sync.aligned.m16n8k16.row.col.f32.bf16.bf16.f32 "
        "{%0,%1,%2,%3}, {%4,%5,%6,%7}, {%8,%9}, {%0,%1,%2,%3};"
        : "+f"(c[0]), "+f"(c[1]), "+f"(c[2]), "+f"(c[3])
        : "r"(a[0]), "r"(a[1]), "r"(a[2]), "r"(a[3]), "r"(b[0]), "r"(b[1]));
}

// Split two fp32 into packed bf16x2 hi and lo(residual) words. x -> low half.
__device__ __forceinline__ void split2(float x, float y, uint32_t& hi, uint32_t& lo) {
    __nv_bfloat16 hx = __float2bfloat16(x), hy = __float2bfloat16(y);
    __nv_bfloat162 hp = __nv_bfloat162(hx, hy);
    __nv_bfloat162 lp = __floats2bfloat162_rn(x - __bfloat162float(hx),
                                              y - __bfloat162float(hy));
    hi = *(uint32_t*)&hp;
    lo = *(uint32_t*)&lp;
}

// ===========================================================================
// Scratch (device globals — no allocation allowed)
// ===========================================================================
__device__ float  g_qkv[BS_ * QKV_];           // fused [4096][6144]: q|k|v
__device__ float2 g_cs[S_ * 64];

// bf16 hi/lo splits
__device__ __nv_bfloat16 g_hs_hi[BS_ * H_],   g_hs_lo[BS_ * H_];
__device__ __nv_bfloat16 g_ao_hi[BS_ * H_],   g_ao_lo[BS_ * H_];   // written by attention
__device__ __nv_bfloat16 g_wqkv_hi[QKV_ * H_], g_wqkv_lo[QKV_ * H_]; // [6144][4096]
__device__ __nv_bfloat16 g_wo_hi[H_ * H_],    g_wo_lo[H_ * H_];

// ===========================================================================
// fp32 -> bf16 hi/lo elementwise split
// ===========================================================================
__global__ void split_k(const float* __restrict__ src,
                        __nv_bfloat16* __restrict__ hi,
                        __nv_bfloat16* __restrict__ lo, int n) {
    int i = blockIdx.x * blockDim.x + threadIdx.x;
    if (i >= n) return;
    float a = src[i];
    __nv_bfloat16 h = __float2bfloat16(a);
    hi[i] = h;
    lo[i] = __float2bfloat16(a - __bfloat162float(h));
}

// fp32 [K][N] -> transposed bf16 hi/lo [N][K]
__global__ void transpose_split_k(const float* __restrict__ src,
                                  __nv_bfloat16* __restrict__ hi,
                                  __nv_bfloat16* __restrict__ lo,
                                  int K, int N) {
    __shared__ float t[32][33];
    int k0 = blockIdx.y * 32, n0 = blockIdx.x * 32;
    int tx = threadIdx.x, ty = threadIdx.y;       // block (32, 8)
#pragma unroll
    for (int i = ty; i < 32; i += 8)
        t[i][tx] = src[(size_t)(k0 + i) * N + n0 + tx];
    __syncthreads();
#pragma unroll
    for (int i = ty; i < 32; i += 8) {
        float a = t[tx][i];
        __nv_bfloat16 h = __float2bfloat16(a);
        size_t o = (size_t)(n0 + i) * K + k0 + tx;
        hi[o] = h;
        lo[o] = __float2bfloat16(a - __bfloat162float(h));
    }
}

// ===========================================================================
// bf16-3-split GEMM on mma.sync.m16n8k16 — exact R14 structure (best: 4077us)
// + drain fix: iterations with no new load commit an EMPTY group so
// CP_WAIT(2) always guarantees stage ks has landed (R14 relied on timing).
// C[M,N] = A[M,K] @ B^T,  A=[M][K] hi/lo, B=[N][K] hi/lo (K-major).
// CTA tile 128x128, 8 warps (2x4), warp tile 64x32. 4-stage K16 pipeline,
// one __syncthreads per stage. Stage stride 24 bf16 (48B), conflict-free.
// ===========================================================================
#define GLD2    24
#define ARR2_B  (128 * GLD2 * 2)      // 6144 B per array per stage
#define STG2_B  (4 * ARR2_B)          // 24576 B (Ah, Al, Bh, Bl)
#define NSTG    4
#define GSMEM_B (NSTG * STG2_B)       // 98304 B

__device__ __forceinline__ void g2_load(
    uint32_t sb, const __nv_bfloat16* Ah, const __nv_bfloat16* Al,
    const __nv_bfloat16* Bh, const __nv_bfloat16* Bl,
    int m0, int n0, int ks, int Kdim, int tid) {
    const int row = tid >> 1;                     // 0..127
    const int ch  = tid & 1;                      // 16B chunk (8 bf16)
    const uint32_t so = (uint32_t)(row * GLD2) * 2 + (uint32_t)ch * 16;
    const size_t gao = (size_t)(m0 + row) * Kdim + ks * 16 + ch * 8;
    const size_t gbo = (size_t)(n0 + row) * Kdim + ks * 16 + ch * 8;
    cp16(sb + 0 * ARR2_B + so, Ah + gao);
    cp16(sb + 1 * ARR2_B + so, Al + gao);
    cp16(sb + 2 * ARR2_B + so, Bh + gbo);
    cp16(sb + 3 * ARR2_B + so, Bl + gbo);
}

__global__ __launch_bounds__(256)
void gemm_bf16_mma(const __nv_bfloat16* __restrict__ Ahi,
                   const __nv_bfloat16* __restrict__ Alo,
                   const __nv_bfloat16* __restrict__ Bhi,
                   const __nv_bfloat16* __restrict__ Blo,
                   float* __restrict__ C, int Ndim, int Kdim) {
    extern __shared__ char smem[];
    const uint32_t sb0 = smem_u32(smem);

    const int tid  = threadIdx.x;
    const int lane = tid & 31;
    const int wid  = tid >> 5;
    const int wm0  = (wid >> 2) * 64;
    const int wn0  = (wid & 3) * 32;
    const int m0 = blockIdx.y * 128;
    const int n0 = blockIdx.x * 128;

    const int rowA  = lane & 15;
    const int koffA = (lane & 16) ? 8 : 0;
    const int rowB  = (lane & 7) + ((lane & 16) ? 8 : 0);
    const int koffB = (lane & 8) ? 8 : 0;
    const uint32_t aoff = (uint32_t)((wm0 + rowA) * GLD2 + koffA) * 2;
    const uint32_t boff = (uint32_t)((wn0 + rowB) * GLD2 + koffB) * 2;

    float acc[4][4][4];
#pragma unroll
    for (int i = 0; i < 4; i++)
#pragma unroll
        for (int j = 0; j < 4; j++)
#pragma unroll
            for (int c = 0; c < 4; c++) acc[i][j][c] = 0.0f;

    const int nks = Kdim >> 4;                    // K / 16 stages

    // Prologue: 3 stages in flight
#pragma unroll
    for (int s = 0; s < NSTG - 1; s++) {
        g2_load(sb0 + s * STG2_B, Ahi, Alo, Bhi, Blo, m0, n0, s, Kdim, tid);
        CP_COMMIT();
    }

    for (int ks = 0; ks < nks; ks++) {
        CP_WAIT(2);                               // stage ks landed (invariant)
        __syncthreads();                          // visible to all; buffers free
        if (ks + NSTG - 1 < nks) {
            g2_load(sb0 + ((ks + NSTG - 1) & (NSTG - 1)) * STG2_B,
                    Ahi, Alo, Bhi, Blo, m0, n0, ks + NSTG - 1, Kdim, tid);
            CP_COMMIT();
        } else {
            CP_COMMIT();                          // empty group: keep wait math exact
        }

        const uint32_t st = sb0 + (ks & (NSTG - 1)) * STG2_B;
        uint32_t ah[4][4], al[4][4], bh[2][4], bl[2][4];
#pragma unroll
        for (int mf = 0; mf < 4; mf++) {
            uint32_t ao = st + aoff + (uint32_t)(mf * 16 * GLD2) * 2;
            ldm_x4(ah[mf], ao);
            ldm_x4(al[mf], ao + ARR2_B);
        }
#pragma unroll
        for (int nf2 = 0; nf2 < 2; nf2++) {
            uint32_t bo = st + 2 * ARR2_B + boff + (uint32_t)(nf2 * 16 * GLD2) * 2;
            ldm_x4(bh[nf2], bo);
            ldm_x4(bl[nf2], bo + ARR2_B);
        }
#pragma unroll
        for (int mf = 0; mf < 4; mf++)
#pragma unroll
            for (int nf = 0; nf < 4; nf++) {
                const uint32_t* ph = &bh[nf >> 1][(nf & 1) * 2];
                const uint32_t* pl = &bl[nf >> 1][(nf & 1) * 2];
                mma_bf16(acc[mf][nf], ah[mf], ph);   // Ah*Bh
                mma_bf16(acc[mf][nf], ah[mf], pl);   // Ah*Bl
                mma_bf16(acc[mf][nf], al[mf], ph);   // Al*Bh
            }
    }

    const int erow = m0 + wm0 + (lane >> 2);
    const int ecol = n0 + wn0 + (lane & 3) * 2;
#pragma unroll
    for (int mf = 0; mf < 4; mf++)
#pragma unroll
        for (int nf = 0; nf < 4; nf++) {
            float* c = acc[mf][nf];
            float* p0 = C + (size_t)(erow + mf * 16) * Ndim + ecol + nf * 8;
            float* p1 = p0 + 8 * (size_t)Ndim;
            *(float2*)p0 = make_float2(c[0], c[1]);
            *(float2*)p1 = make_float2(c[2], c[3]);
        }
}

// ===========================================================================
// RoPE table + apply (apply generalized to the fused strided layout)
// ===========================================================================
__global__ void rope_table_k() {
    int i = blockIdx.x * blockDim.x + threadIdx.x;
    if (i >= S_ * 64) return;
    int p = i >> 6, d = i & 63;
    float invf = 1.0f / powf(10000.0f, (float)(2 * d) * (1.0f / 128.0f));
    float fr = (float)p * invf;
    g_cs[i] = make_float2(cosf(fr), sinf(fr));
}

// x rows have stride QKV_; this call covers nheads heads starting at colbase.
__global__ void rope_apply_k(float* __restrict__ x, int nheads, int colbase) {
    int i = blockIdx.x * blockDim.x + threadIdx.x;
    int total = BS_ * nheads * 64;
    if (i >= total) return;
    int d   = i & 63;
    int hh  = (i >> 6) % nheads;
    int row = (i >> 6) / nheads;
    int p   = row % S_;
    float2 cs = g_cs[p * 64 + d];
    float* base = x + (size_t)row * QKV_ + colbase + hh * HD_;
    float x1 = base[d], x2 = base[d + 64];
    base[d]      = x1 * cs.x - x2 * cs.y;
    base[d + 64] = x2 * cs.x + x1 * cs.y;
}

// ===========================================================================
// Tensor-core flash attention (R13 structure — verified; now reads the
// fused qkv buffer: row stride QKV_, q at col 0, k at 4096, v at 5120)
// ===========================================================================
#define AT_LDA 136
#define AT_QH  0
#define AT_QL  (128 * AT_LDA)
#define AT_KH  (2 * 128 * AT_LDA)
#define AT_KL  (AT_KH + 64 * AT_LDA)
#define AT_VH  (AT_KL + 64 * AT_LDA)
#define AT_VL  (AT_VH + 64 * AT_LDA)
#define AT_SMEM_BYTES ((AT_VL + 64 * AT_LDA) * 2)   // 139264

__global__ __launch_bounds__(256)
void flash_attn_tc(const float* __restrict__ QKVg,
                   __nv_bfloat16* __restrict__ Ohi,
                   __nv_bfloat16* __restrict__ Olo) {
    extern __shared__ __nv_bfloat16 sb_at[];
    const int qi  = (int)gridDim.x - 1 - (int)blockIdx.x;   // big tiles first
    const int h   = blockIdx.y;
    const int b   = blockIdx.z;
    const int kvh = h >> 2;
    const int tid = threadIdx.x, lane = tid & 31, wid = tid >> 5;
    const int q0  = qi * 128;
    const int wm  = wid * 16;
    const float scale = 0.08838834764831845f;      // 1/sqrt(128)
    const uint32_t sbase = smem_u32(sb_at);

    // --- Stage Q tile (128 x 128 fp32 -> hi/lo bf16 smem) ---
    {
        const int row = tid >> 1, half = tid & 1;
        const float* src = QKVg + (size_t)(b * S_ + q0 + row) * QKV_ + h * HD_ + half * 64;
        __nv_bfloat16* dh = sb_at + AT_QH + row * AT_LDA + half * 64;
        __nv_bfloat16* dl = sb_at + AT_QL + row * AT_LDA + half * 64;
#pragma unroll
        for (int i = 0; i < 16; i++) {
            float4 v = *(const float4*)(src + i * 4);
            uint32_t h0, l0, h1, l1;
            split2(v.x, v.y, h0, l0);
            split2(v.z, v.w, h1, l1);
            *(uint32_t*)(dh + i * 4)     = h0;
            *(uint32_t*)(dh + i * 4 + 2) = h1;
            *(uint32_t*)(dl + i * 4)     = l0;
            *(uint32_t*)(dl + i * 4 + 2) = l1;
        }
    }

    const int rA = lane & 15;
    const int kA = (lane & 16) ? 8 : 0;
    const int rB = (lane & 7) + ((lane & 16) ? 8 : 0);
    const int kB = (lane & 8) ? 8 : 0;

    float Oa[16][4];
#pragma unroll
    for (int i = 0; i < 16; i++)
#pragma unroll
        for (int c = 0; c < 4; c++) Oa[i][c] = 0.0f;
    float m0 = -1e30f, m1 = -1e30f, l0 = 0.0f, l1 = 0.0f;

    const int row_lo = q0 + wm + (lane >> 2);
    const int row_hi = row_lo + 8;
    const int ntiles = 2 * (qi + 1);

    for (int t = 0; t < ntiles; t++) {
        const int kv0 = t * 64;
        __syncthreads();   // smem reuse guard (also orders Q stores on t==0)

        // --- Load + split K/V tile (64 x 128 fp32 each) ---
        {
            const int row = tid >> 2, qtr = tid & 3;
            const size_t go = (size_t)(b * S_ + kv0 + row) * QKV_ + kvh * HD_ + qtr * 32;
            const float* sk = QKVg + go + H_;           // k block at col 4096
            const float* sv = QKVg + go + H_ + KV_;     // v block at col 5120
            __nv_bfloat16* kh = sb_at + AT_KH + row * AT_LDA + qtr * 32;
            __nv_bfloat16* kl = sb_at + AT_KL + row * AT_LDA + qtr * 32;
            __nv_bfloat16* vh = sb_at + AT_VH + row * AT_LDA + qtr * 32;
            __nv_bfloat16* vl = sb_at + AT_VL + row * AT_LDA + qtr * 32;
#pragma unroll
            for (int i = 0; i < 8; i++) {
                float4 kv4 = *(const float4*)(sk + i * 4);
                uint32_t h0, lo0, h1, lo1;
                split2(kv4.x, kv4.y, h0, lo0);
                split2(kv4.z, kv4.w, h1, lo1);
                *(uint32_t*)(kh + i * 4) = h0; *(uint32_t*)(kh + i * 4 + 2) = h1;
                *(uint32_t*)(kl + i * 4) = lo0; *(uint32_t*)(kl + i * 4 + 2) = lo1;
                float4 vv4 = *(const float4*)(sv + i * 4);
                split2(vv4.x, vv4.y, h0, lo0);
                split2(vv4.z, vv4.w, h1, lo1);
                *(uint32_t*)(vh + i * 4) = h0; *(uint32_t*)(vh + i * 4 + 2) = h1;
                *(uint32_t*)(vl + i * 4) = lo0; *(uint32_t*)(vl + i * 4 + 2) = lo1;
            }
        }
        __syncthreads();

        // --- S = Q @ K^T (3-split), m16 x n64 per warp, fp32 accum ---
        float sc[8][4];
#pragma unroll
        for (int nf = 0; nf < 8; nf++)
#pragma unroll
            for (int c = 0; c < 4; c++) sc[nf][c] = 0.0f;

#pragma unroll
        for (int ks = 0; ks < 8; ks++) {
            uint32_t ah[4], al[4];
            uint32_t aaddr = sbase + 2u * (AT_QH + (wm + rA) * AT_LDA + ks * 16 + kA);
            ldm_x4(ah, aaddr);
            ldm_x4(al, aaddr + 2u * (AT_QL - AT_QH));
            uint32_t bh[4][4], bl[4][4];
#pragma unroll
            for (int n2 = 0; n2 < 4; n2++) {
                uint32_t baddr = sbase + 2u * (AT_KH + (n2 * 16 + rB) * AT_LDA + ks * 16 + kB);
                ldm_x4(bh[n2], baddr);
                ldm_x4(bl[n2], baddr + 2u * (AT_KL - AT_KH));
            }
#pragma unroll
            for (int nf = 0; nf < 8; nf++) {
                const uint32_t* ph = &bh[nf >> 1][(nf & 1) * 2];
                const uint32_t* pl = &bl[nf >> 1][(nf & 1) * 2];
                mma_bf16(sc[nf], ah, ph);
                mma_bf16(sc[nf], ah, pl);
                mma_bf16(sc[nf], al, ph);
            }
        }

        // --- Mask + scale + online softmax ---
        float mx0 = -1e30f, mx1 = -1e30f;
#pragma unroll
        for (int nf = 0; nf < 8; nf++) {
            const int c0 = kv0 + nf * 8 + 2 * (lane & 3);
            sc[nf][0] = (c0     <= row_lo) ? sc[nf][0] * scale : -1e30f;
            sc[nf][1] = (c0 + 1 <= row_lo) ? sc[nf][1] * scale : -1e30f;
            sc[nf][2] = (c0     <= row_hi) ? sc[nf][2] * scale : -1e30f;
            sc[nf][3] = (c0 + 1 <= row_hi) ? sc[nf][3] * scale : -1e30f;
            mx0 = fmaxf(mx0, fmaxf(sc[nf][0], sc[nf][1]));
            mx1 = fmaxf(mx1, fmaxf(sc[nf][2], sc[nf][3]));
        }
        mx0 = fmaxf(mx0, __shfl_xor_sync(0xffffffffu, mx0, 1));
        mx0 = fmaxf(mx0, __shfl_xor_sync(0xffffffffu, mx0, 2));
        mx1 = fmaxf(mx1, __shfl_xor_sync(0xffffffffu, mx1, 1));
        mx1 = fmaxf(mx1, __shfl_xor_sync(0xffffffffu, mx1, 2));

        const float mn0 = fmaxf(m0, mx0), mn1 = fmaxf(m1, mx1);
        const float a0 = __expf(m0 - mn0), a1 = __expf(m1 - mn1);
        float s0 = 0.0f, s1 = 0.0f;
#pragma unroll
        for (int nf = 0; nf < 8; nf++) {
            sc[nf][0] = __expf(sc[nf][0] - mn0);
            sc[nf][1] = __expf(sc[nf][1] - mn0);
            sc[nf][2] = __expf(sc[nf][2] - mn1);
            sc[nf][3] = __expf(sc[nf][3] - mn1);
            s0 += sc[nf][0] + sc[nf][1];
            s1 += sc[nf][2] + sc[nf][3];
        }
        s0 += __shfl_xor_sync(0xffffffffu, s0, 1);
        s0 += __shfl_xor_sync(0xffffffffu, s0, 2);
        s1 += __shfl_xor_sync(0xffffffffu, s1, 1);
        s1 += __shfl_xor_sync(0xffffffffu, s1, 2);
        l0 = l0 * a0 + s0;
        l1 = l1 * a1 + s1;
        m0 = mn0; m1 = mn1;
#pragma unroll
        for (int i = 0; i < 16; i++) {
            Oa[i][0] *= a0; Oa[i][1] *= a0;
            Oa[i][2] *= a1; Oa[i][3] *= a1;
        }

        // --- O += P @ V (3-split; V via trans-ldmatrix) ---
#pragma unroll
        for (int kc = 0; kc < 4; kc++) {
            uint32_t pah[4], pal[4];
            split2(sc[2*kc][0],   sc[2*kc][1],   pah[0], pal[0]);
            split2(sc[2*kc][2],   sc[2*kc][3],   pah[1], pal[1]);
            split2(sc[2*kc+1][0], sc[2*kc+1][1], pah[2], pal[2]);
            split2(sc[2*kc+1][2], sc[2*kc+1][3], pah[3], pal[3]);
#pragma unroll
            for (int n2 = 0; n2 < 8; n2++) {
                uint32_t bvh[4], bvl[4];
                uint32_t vaddr = sbase + 2u * (AT_VH + (kc * 16 + rA) * AT_LDA + n2 * 16 + kA);
                ldm_x4_t(bvh, vaddr);
                ldm_x4_t(bvl, vaddr + 2u * (AT_VL - AT_VH));
                mma_bf16(Oa[2*n2],     pah, &bvh[0]);
                mma_bf16(Oa[2*n2],     pah, &bvl[0]);
                mma_bf16(Oa[2*n2],     pal, &bvh[0]);
                mma_bf16(Oa[2*n2 + 1], pah, &bvh[2]);
                mma_bf16(Oa[2*n2 + 1], pah, &bvl[2]);
                mma_bf16(Oa[2*n2 + 1], pal, &bvh[2]);
            }
        }
    }

    // --- Epilogue: O / l, write bf16 hi/lo directly (WO GEMM inputs) ---
    const float inv0 = 1.0f / l0, inv1 = 1.0f / l1;
    const size_t base0 = ((size_t)(b * S_ + row_lo) * NH_ + h) * HD_;
    const size_t base1 = ((size_t)(b * S_ + row_hi) * NH_ + h) * HD_;
#pragma unroll
    for (int nf = 0; nf < 16; nf++) {
        const int d = nf * 8 + 2 * (lane & 3);
        uint32_t hh, ll;
        split2(Oa[nf][0] * inv0, Oa[nf][1] * inv0, hh, ll);
        *(uint32_t*)(Ohi + base0 + d) = hh;
        *(uint32_t*)(Olo + base0 + d) = ll;
        split2(Oa[nf][2] * inv1, Oa[nf][3] * inv1, hh, ll);
        *(uint32_t*)(Ohi + base1 + d) = hh;
        *(uint32_t*)(Olo + base1 + d) = ll;
    }
}

// ===========================================================================
// Launch: prep -> ONE fused QKV GEMM (48x32 = 1536 tiles) -> rope ->
// attention -> WO GEMM.
// ===========================================================================
extern "C" void kernel_launch(void* const* d_in, const int* in_sizes, int n_in,
                              void* d_out, int out_size) {
    const float* hs  = (const float*)d_in[0];
    // d_in[1] (position_ids) unused: arange(S) broadcast, computed in-kernel.
    const float* wq  = (const float*)d_in[2];
    const float* wk  = (const float*)d_in[3];
    const float* wv  = (const float*)d_in[4];
    const float* wo  = (const float*)d_in[5];
    float*       out = (float*)d_out;

    float* qkv;
    cudaGetSymbolAddress((void**)&qkv, g_qkv);

    __nv_bfloat16 *hsh, *hsl, *aoh, *aol, *wqkvh, *wqkvl, *woh, *wol;
    cudaGetSymbolAddress((void**)&hsh,   g_hs_hi);
    cudaGetSymbolAddress((void**)&hsl,   g_hs_lo);
    cudaGetSymbolAddress((void**)&aoh,   g_ao_hi);
    cudaGetSymbolAddress((void**)&aol,   g_ao_lo);
    cudaGetSymbolAddress((void**)&wqkvh, g_wqkv_hi);
    cudaGetSymbolAddress((void**)&wqkvl, g_wqkv_lo);
    cudaGetSymbolAddress((void**)&woh,   g_wo_hi);
    cudaGetSymbolAddress((void**)&wol,   g_wo_lo);

    cudaFuncSetAttribute(gemm_bf16_mma, cudaFuncAttributeMaxDynamicSharedMemorySize,
                         GSMEM_B);
    cudaFuncSetAttribute(flash_attn_tc, cudaFuncAttributeMaxDynamicSharedMemorySize,
                         AT_SMEM_BYTES);

    // Prep: activation split + transposed weights into the fused wqkv buffer
    split_k<<<(BS_ * H_ + 255) / 256, 256>>>(hs, hsh, hsl, BS_ * H_);
    transpose_split_k<<<dim3(H_ / 32,  H_ / 32), dim3(32, 8)>>>(
        wq, wqkvh, wqkvl, H_, H_);
    transpose_split_k<<<dim3(KV_ / 32, H_ / 32), dim3(32, 8)>>>(
        wk, wqkvh + (size_t)H_ * H_, wqkvl + (size_t)H_ * H_, H_, KV_);
    transpose_split_k<<<dim3(KV_ / 32, H_ / 32), dim3(32, 8)>>>(
        wv, wqkvh + (size_t)(H_ + KV_) * H_, wqkvl + (size_t)(H_ + KV_) * H_, H_, KV_);
    transpose_split_k<<<dim3(H_ / 32,  H_ / 32), dim3(32, 8)>>>(wo, woh, wol, H_, H_);

    // Fused QKV projection: C [4096][6144]
    gemm_bf16_mma<<<dim3(QKV_ / 128, BS_ / 128), 256, GSMEM_B>>>(
        hsh, hsl, wqkvh, wqkvl, qkv, QKV_, H_);

    rope_table_k<<<(S_ * 64 + 255) / 256, 256>>>();
    rope_apply_k<<<(BS_ * NH_  * 64) / 256, 256>>>(qkv, NH_, 0);     // q heads
    rope_apply_k<<<(BS_ * NKV_ * 64) / 256, 256>>>(qkv, NKV_, H_);   // k heads

    flash_attn_tc<<<dim3(S_ / 128, NH_, B_), 256, AT_SMEM_BYTES>>>(qkv, aoh, aol);

    gemm_bf16_mma<<<dim3(H_ / 128, BS_ / 128), 256, GSMEM_B>>>(
        aoh, aol, woh, wol, out, H_, H_);
}